// round 2
// baseline (speedup 1.0000x reference)
#include <cuda_runtime.h>
#include <math.h>

#define BB 2
#define SS 2048
#define DD 1024
#define HH 16
#define HD 64

// Scratch: q,k,v in head-major [B,H,S,HD]; attn output in [B,S,D]
__device__ float g_q[BB*HH*SS*HD];
__device__ float g_k[BB*HH*SS*HD];
__device__ float g_v[BB*HH*SS*HD];
__device__ float g_attn[BB*SS*DD];

// ---------------------------------------------------------------------------
// NT SGEMM: C[m,n] = sum_k A[m,k]*W[n,k] + bias[n]
// A: [M=4096, K=1024] row-major, W: [N=1024, K=1024] row-major.
// 128x128x16 block tile, 256 threads, 8x8 per-thread micro-tile.
// mode 0: store to head-major qkv layout; mode 1: plain [row*DD+col] store.
// ---------------------------------------------------------------------------
__global__ __launch_bounds__(256) void gemm_nt(const float* __restrict__ A,
                                               const float* __restrict__ W,
                                               const float* __restrict__ bias,
                                               float* __restrict__ C,
                                               int mode)
{
    __shared__ float As[16][132];   // [k][m], stride 132 (16B aligned, bank-spread)
    __shared__ float Bs[16][132];   // [k][n]

    const int tid = threadIdx.x;
    const int tx  = tid & 15;       // column group
    const int ty  = tid >> 4;       // row group
    const int m0  = blockIdx.y * 128;
    const int n0  = blockIdx.x * 128;

    float acc[8][8];
#pragma unroll
    for (int i = 0; i < 8; ++i)
#pragma unroll
        for (int j = 0; j < 8; ++j) acc[i][j] = 0.0f;

    for (int k0 = 0; k0 < DD; k0 += 16) {
        // Load 128x16 tiles of A and W (transposed into smem). 512 float4s each.
#pragma unroll
        for (int it = 0; it < 2; ++it) {
            int f   = tid + it * 256;        // 0..511
            int row = f >> 2;                // 0..127
            int kq  = f & 3;                 // float4 slot within 16 k's
            float4 a4 = *(const float4*)&A[(size_t)(m0 + row) * DD + k0 + kq * 4];
            As[kq*4+0][row] = a4.x; As[kq*4+1][row] = a4.y;
            As[kq*4+2][row] = a4.z; As[kq*4+3][row] = a4.w;
            float4 b4 = *(const float4*)&W[(size_t)(n0 + row) * DD + k0 + kq * 4];
            Bs[kq*4+0][row] = b4.x; Bs[kq*4+1][row] = b4.y;
            Bs[kq*4+2][row] = b4.z; Bs[kq*4+3][row] = b4.w;
        }
        __syncthreads();

#pragma unroll
        for (int k = 0; k < 16; ++k) {
            float a[8], b[8];
            *(float4*)&a[0] = *(const float4*)&As[k][ty * 4];
            *(float4*)&a[4] = *(const float4*)&As[k][64 + ty * 4];
            *(float4*)&b[0] = *(const float4*)&Bs[k][tx * 4];
            *(float4*)&b[4] = *(const float4*)&Bs[k][64 + tx * 4];
#pragma unroll
            for (int i = 0; i < 8; ++i)
#pragma unroll
                for (int j = 0; j < 8; ++j)
                    acc[i][j] = fmaf(a[i], b[j], acc[i][j]);
        }
        __syncthreads();
    }

    // Epilogue: bias + store
#pragma unroll
    for (int i = 0; i < 8; ++i) {
        int row = m0 + ((i < 4) ? (ty * 4 + i) : (64 + ty * 4 + (i - 4)));
#pragma unroll
        for (int j = 0; j < 8; ++j) {
            int col = n0 + ((j < 4) ? (tx * 4 + j) : (64 + tx * 4 + (j - 4)));
            float v = acc[i][j] + bias[col];
            if (mode == 0) {
                // row = b*S + s ; col = h*HD + hd  ->  [B,H,S,HD]
                int b  = row >> 11;          // /2048
                int s  = row & 2047;
                int h_ = col >> 6;           // /64
                int hd = col & 63;
                C[((size_t)(b * HH + h_) * SS + s) * HD + hd] = v;
            } else {
                C[(size_t)row * DD + col] = v;
            }
        }
    }
}

// ---------------------------------------------------------------------------
// Flash attention, fp32. One block = one (b,h) and one 64-row q tile.
// 256 threads; thread owns 4x4 micro-tile: rows {ty+16*ii}, cols {tx+16*jj}.
// Online softmax, causal mask on diagonal tile only, k-loop ends at diagonal.
// ---------------------------------------------------------------------------
__global__ __launch_bounds__(256) void attn_kernel()
{
    extern __shared__ float sm[];
    const int STR = 68;                  // row stride: 16B aligned, banks spread
    float* Qs = sm;                      // 64 x STR
    float* Ks = Qs + 64 * STR;
    float* Vs = Ks + 64 * STR;
    float* Ps = Vs + 64 * STR;

    const int qt = blockIdx.x;           // q tile (0..31)
    const int bh = blockIdx.y;           // b*H + h (0..31)
    const int q0 = qt * 64;

    const float* qp = g_q + (size_t)bh * SS * HD;
    const float* kp = g_k + (size_t)bh * SS * HD;
    const float* vp = g_v + (size_t)bh * SS * HD;

    const int tid = threadIdx.x;
    const int tx  = tid & 15;
    const int ty  = tid >> 4;

    // Load Q tile (64x64 floats = 1024 float4s)
#pragma unroll
    for (int it = 0; it < 4; ++it) {
        int f   = tid + it * 256;
        int row = f >> 4;
        int dq  = f & 15;
        *(float4*)&Qs[row * STR + dq * 4] =
            *(const float4*)&qp[(size_t)(q0 + row) * HD + dq * 4];
    }

    float m_r[4], l_r[4], o_acc[4][4];
#pragma unroll
    for (int ii = 0; ii < 4; ++ii) {
        m_r[ii] = -1e30f; l_r[ii] = 0.0f;
#pragma unroll
        for (int jj = 0; jj < 4; ++jj) o_acc[ii][jj] = 0.0f;
    }

    const float scale = 0.125f;          // 1/sqrt(64)

    for (int kt = 0; kt <= qt; ++kt) {
        const int k0 = kt * 64;
        // Load K, V tiles
#pragma unroll
        for (int it = 0; it < 4; ++it) {
            int f   = tid + it * 256;
            int row = f >> 4;
            int dq  = f & 15;
            *(float4*)&Ks[row * STR + dq * 4] =
                *(const float4*)&kp[(size_t)(k0 + row) * HD + dq * 4];
            *(float4*)&Vs[row * STR + dq * 4] =
                *(const float4*)&vp[(size_t)(k0 + row) * HD + dq * 4];
        }
        __syncthreads();

        // Scores: s[ii][jj] = Q[row_i] . K[col_j]
        float s[4][4];
#pragma unroll
        for (int ii = 0; ii < 4; ++ii)
#pragma unroll
            for (int jj = 0; jj < 4; ++jj) s[ii][jj] = 0.0f;

#pragma unroll
        for (int d = 0; d < 64; d += 4) {
            float4 q4[4], k4[4];
#pragma unroll
            for (int ii = 0; ii < 4; ++ii)
                q4[ii] = *(const float4*)&Qs[(ty + 16 * ii) * STR + d];
#pragma unroll
            for (int jj = 0; jj < 4; ++jj)
                k4[jj] = *(const float4*)&Ks[(tx + 16 * jj) * STR + d];
#pragma unroll
            for (int ii = 0; ii < 4; ++ii)
#pragma unroll
                for (int jj = 0; jj < 4; ++jj) {
                    s[ii][jj] = fmaf(q4[ii].x, k4[jj].x, s[ii][jj]);
                    s[ii][jj] = fmaf(q4[ii].y, k4[jj].y, s[ii][jj]);
                    s[ii][jj] = fmaf(q4[ii].z, k4[jj].z, s[ii][jj]);
                    s[ii][jj] = fmaf(q4[ii].w, k4[jj].w, s[ii][jj]);
                }
        }

        // Scale + causal mask (diagonal tile only)
        const bool diag = (kt == qt);
#pragma unroll
        for (int ii = 0; ii < 4; ++ii) {
            int grow = q0 + ty + 16 * ii;
#pragma unroll
            for (int jj = 0; jj < 4; ++jj) {
                int gcol = k0 + tx + 16 * jj;
                float v = s[ii][jj] * scale;
                if (diag && gcol > grow) v = -1e30f;
                s[ii][jj] = v;
            }
        }

        // Online softmax per row
#pragma unroll
        for (int ii = 0; ii < 4; ++ii) {
            float mt = fmaxf(fmaxf(s[ii][0], s[ii][1]), fmaxf(s[ii][2], s[ii][3]));
#pragma unroll
            for (int off = 8; off > 0; off >>= 1)
                mt = fmaxf(mt, __shfl_xor_sync(0xffffffffu, mt, off));
            float mn = fmaxf(m_r[ii], mt);
            float alpha = __expf(m_r[ii] - mn);
            m_r[ii] = mn;
            l_r[ii] *= alpha;
#pragma unroll
            for (int jj = 0; jj < 4; ++jj) o_acc[ii][jj] *= alpha;

            float rs = 0.0f;
#pragma unroll
            for (int jj = 0; jj < 4; ++jj) {
                float p = __expf(s[ii][jj] - mn);
                s[ii][jj] = p;
                rs += p;
            }
#pragma unroll
            for (int off = 8; off > 0; off >>= 1)
                rs += __shfl_xor_sync(0xffffffffu, rs, off);
            l_r[ii] += rs;

#pragma unroll
            for (int jj = 0; jj < 4; ++jj)
                Ps[(ty + 16 * ii) * STR + tx + 16 * jj] = s[ii][jj];
        }
        __syncthreads();

        // PV: o_acc[ii][jj] += sum_k P[row_i][k] * V[k][col_j]
#pragma unroll
        for (int k = 0; k < 64; k += 4) {
            float4 p4[4];
#pragma unroll
            for (int ii = 0; ii < 4; ++ii)
                p4[ii] = *(const float4*)&Ps[(ty + 16 * ii) * STR + k];
#pragma unroll
            for (int t = 0; t < 4; ++t) {
                float vv[4];
#pragma unroll
                for (int jj = 0; jj < 4; ++jj)
                    vv[jj] = Vs[(k + t) * STR + tx + 16 * jj];
#pragma unroll
                for (int ii = 0; ii < 4; ++ii) {
                    const float* pf = (const float*)&p4[ii];
                    float pv = pf[t];
#pragma unroll
                    for (int jj = 0; jj < 4; ++jj)
                        o_acc[ii][jj] = fmaf(pv, vv[jj], o_acc[ii][jj]);
                }
            }
        }
        __syncthreads();
    }

    // Normalize and write to [B,S,D]
    const int b  = bh >> 4;
    const int h_ = bh & 15;
#pragma unroll
    for (int ii = 0; ii < 4; ++ii) {
        float inv = 1.0f / l_r[ii];
        int row = q0 + ty + 16 * ii;
#pragma unroll
        for (int jj = 0; jj < 4; ++jj) {
            int col = tx + 16 * jj;
            g_attn[((size_t)b * SS + row) * DD + h_ * HD + col] = o_acc[ii][jj] * inv;
        }
    }
}

// ---------------------------------------------------------------------------
extern "C" void kernel_launch(void* const* d_in, const int* in_sizes, int n_in,
                              void* d_out, int out_size)
{
    const float* h  = (const float*)d_in[0];
    const float* Wq = (const float*)d_in[1];
    const float* bq = (const float*)d_in[2];
    const float* Wk = (const float*)d_in[3];
    const float* bk = (const float*)d_in[4];
    const float* Wv = (const float*)d_in[5];
    const float* bv = (const float*)d_in[6];
    const float* Wo = (const float*)d_in[7];
    const float* bo = (const float*)d_in[8];
    float* out = (float*)d_out;

    float *dq, *dk, *dv, *da;
    cudaGetSymbolAddress((void**)&dq, g_q);
    cudaGetSymbolAddress((void**)&dk, g_k);
    cudaGetSymbolAddress((void**)&dv, g_v);
    cudaGetSymbolAddress((void**)&da, g_attn);

    dim3 ggrid(DD / 128, (BB * SS) / 128);   // (8, 32)

    gemm_nt<<<ggrid, 256>>>(h, Wq, bq, dq, 0);
    gemm_nt<<<ggrid, 256>>>(h, Wk, bk, dk, 0);
    gemm_nt<<<ggrid, 256>>>(h, Wv, bv, dv, 0);

    const int ATTN_SMEM = 4 * 64 * 68 * (int)sizeof(float);   // 69632 B
    cudaFuncSetAttribute(attn_kernel, cudaFuncAttributeMaxDynamicSharedMemorySize,
                         ATTN_SMEM);
    attn_kernel<<<dim3(SS / 64, BB * HH), 256, ATTN_SMEM>>>();

    gemm_nt<<<ggrid, 256>>>(da, Wo, bo, out, 1);
}

// round 8
// speedup vs baseline: 2.0541x; 2.0541x over previous
#include <cuda_runtime.h>
#include <cuda_bf16.h>
#include <cstdint>
#include <math.h>

#define BB 2
#define SS 2048
#define DD 1024
#define HH 16
#define HD 64

// Scratch: q,k,v head-major [B,H,S,HD]; attn output [B,S,D]
__device__ float g_q[BB*HH*SS*HD];
__device__ float g_k[BB*HH*SS*HD];
__device__ float g_v[BB*HH*SS*HD];
__device__ float g_attn[BB*SS*DD];

// ===========================================================================
// Helpers: ldmatrix / mma.sync bf16 / fp32 split-pack
// ===========================================================================
__device__ __forceinline__ uint32_t smem_u32(const void* p) {
    uint32_t a;
    asm("{ .reg .u64 t; cvta.to.shared.u64 t, %1; cvt.u32.u64 %0, t; }"
        : "=r"(a) : "l"(p));
    return a;
}
__device__ __forceinline__ void ldsm4(uint32_t* r, uint32_t a) {
    asm volatile("ldmatrix.sync.aligned.m8n8.x4.shared.b16 {%0,%1,%2,%3}, [%4];"
                 : "=r"(r[0]), "=r"(r[1]), "=r"(r[2]), "=r"(r[3]) : "r"(a));
}
__device__ __forceinline__ void ldsm4t(uint32_t* r, uint32_t a) {
    asm volatile("ldmatrix.sync.aligned.m8n8.x4.trans.shared.b16 {%0,%1,%2,%3}, [%4];"
                 : "=r"(r[0]), "=r"(r[1]), "=r"(r[2]), "=r"(r[3]) : "r"(a));
}
__device__ __forceinline__ void mma_bf(float* d, const uint32_t* a, const uint32_t* b) {
    asm volatile("mma.sync.aligned.m16n8k16.row.col.f32.bf16.bf16.f32 "
                 "{%0,%1,%2,%3}, {%4,%5,%6,%7}, {%8,%9}, {%0,%1,%2,%3};"
                 : "+f"(d[0]), "+f"(d[1]), "+f"(d[2]), "+f"(d[3])
                 : "r"(a[0]), "r"(a[1]), "r"(a[2]), "r"(a[3]),
                   "r"(b[0]), "r"(b[1]));
}
// pack the high (bf16-truncated) halves of two fp32: low bf16 = x, high = y
__device__ __forceinline__ uint32_t packhi(float x, float y) {
    uint32_t r;
    asm("prmt.b32 %0, %1, %2, 0x7632;"
        : "=r"(r) : "r"(__float_as_uint(x)), "r"(__float_as_uint(y)));
    return r;
}
// residuals (x - trunc_bf16(x)) rounded to bf16x2
__device__ __forceinline__ uint32_t packlo(float x, float y) {
    float lx = x - __uint_as_float(__float_as_uint(x) & 0xFFFF0000u);
    float ly = y - __uint_as_float(__float_as_uint(y) & 0xFFFF0000u);
    uint32_t r;
    asm("cvt.rn.bf16x2.f32 %0, %1, %2;" : "=r"(r) : "f"(ly), "f"(lx));
    return r;
}

// ===========================================================================
// NT GEMM via mma.sync bf16 3-term compensation:
//   C[m,n] = sum_k A[m,k]*W[n,k] + bias[n]
// Block 128x128x(BK=32). 8 warps: 4(m) x 2(n); warp tile 32m x 64n.
// Smem tiles (bf16): Ahi/Alo [128][32], Bhi/Blo [128][32]; 64B rows,
// granule swizzle g ^= (row & 3). Register prefetch of next k-slab.
// mode 0: head-major [B,H,S,HD] store; mode 1: plain [row,col].
// ===========================================================================
#define AHI 0
#define ALO 8192
#define BHI 16384
#define BLO 24576

__global__ __launch_bounds__(256) void gemm_mma(const float* __restrict__ A,
                                                const float* __restrict__ W,
                                                const float* __restrict__ bias,
                                                float* __restrict__ C, int mode)
{
    __shared__ char sh[32768];
    const uint32_t shb = smem_u32(sh);
    const int tid  = threadIdx.x;
    const int lane = tid & 31;
    const int wid  = tid >> 5;
    const int wm   = wid & 3;
    const int wn   = wid >> 2;
    const int m0   = blockIdx.y * 128;
    const int n0   = blockIdx.x * 128;

    const int frow = tid >> 1;           // 0..127 (tile row for fill)
    const int fcol = (tid & 1) * 16;     // 0 or 16 within the 32-wide k slab

    float acc[2][8][4];
#pragma unroll
    for (int mt = 0; mt < 2; ++mt)
#pragma unroll
        for (int nt = 0; nt < 8; ++nt)
#pragma unroll
            for (int e = 0; e < 4; ++e) acc[mt][nt][e] = 0.0f;

    float4 pa[4], pb[4];
#pragma unroll
    for (int i = 0; i < 4; ++i) {
        pa[i] = *(const float4*)&A[(size_t)(m0 + frow) * DD + fcol + i * 4];
        pb[i] = *(const float4*)&W[(size_t)(n0 + frow) * DD + fcol + i * 4];
    }

    for (int kb = 0; kb < DD / 32; ++kb) {
        __syncthreads();
        // ---- store prefetched slab, split hi/lo ----
#pragma unroll
        for (int gi = 0; gi < 2; ++gi) {
            const float* fa = (const float*)&pa[gi * 2];
            const float* fb = (const float*)&pb[gi * 2];
            int g = (tid & 1) * 2 + gi;
            uint32_t off = (uint32_t)frow * 64 + (((uint32_t)(g ^ (frow & 3))) << 4);
            uint4 h4, l4;
            h4.x = packhi(fa[0], fa[1]); h4.y = packhi(fa[2], fa[3]);
            h4.z = packhi(fa[4], fa[5]); h4.w = packhi(fa[6], fa[7]);
            l4.x = packlo(fa[0], fa[1]); l4.y = packlo(fa[2], fa[3]);
            l4.z = packlo(fa[4], fa[5]); l4.w = packlo(fa[6], fa[7]);
            *(uint4*)(sh + AHI + off) = h4;
            *(uint4*)(sh + ALO + off) = l4;
            h4.x = packhi(fb[0], fb[1]); h4.y = packhi(fb[2], fb[3]);
            h4.z = packhi(fb[4], fb[5]); h4.w = packhi(fb[6], fb[7]);
            l4.x = packlo(fb[0], fb[1]); l4.y = packlo(fb[2], fb[3]);
            l4.z = packlo(fb[4], fb[5]); l4.w = packlo(fb[6], fb[7]);
            *(uint4*)(sh + BHI + off) = h4;
            *(uint4*)(sh + BLO + off) = l4;
        }
        __syncthreads();

        // ---- prefetch next slab (latency hidden under mma) ----
        if (kb + 1 < DD / 32) {
            int kn = (kb + 1) * 32 + fcol;
#pragma unroll
            for (int i = 0; i < 4; ++i) {
                pa[i] = *(const float4*)&A[(size_t)(m0 + frow) * DD + kn + i * 4];
                pb[i] = *(const float4*)&W[(size_t)(n0 + frow) * DD + kn + i * 4];
            }
        }

        // ---- mma over the 2 k16 steps of this slab ----
#pragma unroll
        for (int ks = 0; ks < 2; ++ks) {
            uint32_t ah[2][4], al[2][4];
#pragma unroll
            for (int mt = 0; mt < 2; ++mt) {
                int r = wm * 32 + mt * 16 + (lane & 15);
                int g = ks * 2 + (lane >> 4);
                uint32_t off = (uint32_t)r * 64 + (((uint32_t)(g ^ (r & 3))) << 4);
                ldsm4(ah[mt], shb + AHI + off);
                ldsm4(al[mt], shb + ALO + off);
            }
#pragma unroll
            for (int np = 0; np < 4; ++np) {
                int r = wn * 64 + np * 16 + ((lane >> 4) << 3) + (lane & 7);
                int g = ks * 2 + ((lane >> 3) & 1);
                uint32_t off = (uint32_t)r * 64 + (((uint32_t)(g ^ (r & 3))) << 4);
                uint32_t bh4[4], bl4[4];
                ldsm4(bh4, shb + BHI + off);
                ldsm4(bl4, shb + BLO + off);
#pragma unroll
                for (int t = 0; t < 2; ++t) {
                    int nt = np * 2 + t;
#pragma unroll
                    for (int mt = 0; mt < 2; ++mt) {
                        mma_bf(acc[mt][nt], ah[mt], bh4 + t * 2);
                        mma_bf(acc[mt][nt], al[mt], bh4 + t * 2);
                        mma_bf(acc[mt][nt], ah[mt], bl4 + t * 2);
                    }
                }
            }
        }
    }

    // ---- epilogue ----
#pragma unroll
    for (int mt = 0; mt < 2; ++mt) {
        int r0 = m0 + wm * 32 + mt * 16 + (lane >> 2);
        int r1 = r0 + 8;
#pragma unroll
        for (int nt = 0; nt < 8; ++nt) {
            int col = n0 + wn * 64 + nt * 8 + ((lane & 3) << 1);
            float2 bv = *(const float2*)&bias[col];
            float2 v0 = { acc[mt][nt][0] + bv.x, acc[mt][nt][1] + bv.y };
            float2 v1 = { acc[mt][nt][2] + bv.x, acc[mt][nt][3] + bv.y };
            if (mode == 0) {
                int h_ = col >> 6, hd = col & 63;
                int b0 = r0 >> 11, s0 = r0 & 2047;
                int b1 = r1 >> 11, s1 = r1 & 2047;
                *(float2*)&C[((size_t)(b0 * HH + h_) * SS + s0) * HD + hd] = v0;
                *(float2*)&C[((size_t)(b1 * HH + h_) * SS + s1) * HD + hd] = v1;
            } else {
                *(float2*)&C[(size_t)r0 * DD + col] = v0;
                *(float2*)&C[(size_t)r1 * DD + col] = v1;
            }
        }
    }
}

// ===========================================================================
// Flash attention via mma.sync bf16 3-term compensation.
// Block = (b,h) x 128 q-rows; 8 warps x 16 q-rows each. K/V tiles of 64 keys.
// Q frags persistent in registers (pre-scaled by 1/8). S in C-frags ->
// quad-shfl softmax -> P packed to A-frags in regs -> PV with ldmatrix.trans.
// ===========================================================================
#define QHI 0
#define QLO 16384
#define KHI 0
#define KLO 8192
#define VHI 16384
#define VLO 24576

__global__ __launch_bounds__(256) void attn_mma()
{
    __shared__ char sh[32768];
    const uint32_t shb = smem_u32(sh);
    const int tid  = threadIdx.x;
    const int lane = tid & 31;
    const int wid  = tid >> 5;
    const int qt   = blockIdx.x;
    const int bh   = blockIdx.y;
    const int q0   = qt * 128;

    const float* qp = g_q + (size_t)bh * SS * HD;
    const float* kp = g_k + (size_t)bh * SS * HD;
    const float* vp = g_v + (size_t)bh * SS * HD;

    // ---- stage Q (scaled by 1/8), split hi/lo into smem ----
    {
        int row = tid >> 1;
        int c0  = (tid & 1) * 32;
        float f[32];
#pragma unroll
        for (int i = 0; i < 8; ++i)
            *(float4*)&f[i * 4] = *(const float4*)&qp[(size_t)(q0 + row) * HD + c0 + i * 4];
#pragma unroll
        for (int i = 0; i < 32; ++i) f[i] *= 0.125f;
#pragma unroll
        for (int gi = 0; gi < 4; ++gi) {
            int g = (tid & 1) * 4 + gi;
            uint32_t off = (uint32_t)row * 128 + (((uint32_t)(g ^ (row & 7))) << 4);
            const float* ff = f + gi * 8;
            uint4 h4, l4;
            h4.x = packhi(ff[0], ff[1]); h4.y = packhi(ff[2], ff[3]);
            h4.z = packhi(ff[4], ff[5]); h4.w = packhi(ff[6], ff[7]);
            l4.x = packlo(ff[0], ff[1]); l4.y = packlo(ff[2], ff[3]);
            l4.z = packlo(ff[4], ff[5]); l4.w = packlo(ff[6], ff[7]);
            *(uint4*)(sh + QHI + off) = h4;
            *(uint4*)(sh + QLO + off) = l4;
        }
    }
    __syncthreads();

    // ---- Q fragments to registers (4 k-steps over d=64) ----
    uint32_t qh[4][4], ql[4][4];
#pragma unroll
    for (int ks = 0; ks < 4; ++ks) {
        int r = wid * 16 + (lane & 15);
        int g = ks * 2 + (lane >> 4);
        uint32_t off = (uint32_t)r * 128 + (((uint32_t)(g ^ (r & 7))) << 4);
        ldsm4(qh[ks], shb + QHI + off);
        ldsm4(ql[ks], shb + QLO + off);
    }

    float o[8][4];
#pragma unroll
    for (int nt = 0; nt < 8; ++nt)
#pragma unroll
        for (int e = 0; e < 4; ++e) o[nt][e] = 0.0f;
    float m0r = -1e30f, m1r = -1e30f, l0r = 0.0f, l1r = 0.0f;

    const int frow = tid >> 2;           // 0..63 key row for fills
    const int fc   = (tid & 3) * 16;
    float4 pk[4], pv[4];
#pragma unroll
    for (int i = 0; i < 4; ++i) {
        pk[i] = *(const float4*)&kp[(size_t)frow * HD + fc + i * 4];
        pv[i] = *(const float4*)&vp[(size_t)frow * HD + fc + i * 4];
    }

    const int ktmax = 2 * qt + 2;
    const int warp_last_row = q0 + wid * 16 + 15;

    for (int kt = 0; kt < ktmax; ++kt) {
        __syncthreads();
        // ---- store K/V tiles (split hi/lo) ----
#pragma unroll
        for (int gi = 0; gi < 2; ++gi) {
            int g = (tid & 3) * 2 + gi;
            uint32_t off = (uint32_t)frow * 128 + (((uint32_t)(g ^ (frow & 7))) << 4);
            const float* fk = (const float*)&pk[gi * 2];
            const float* fv = (const float*)&pv[gi * 2];
            uint4 h4, l4;
            h4.x = packhi(fk[0], fk[1]); h4.y = packhi(fk[2], fk[3]);
            h4.z = packhi(fk[4], fk[5]); h4.w = packhi(fk[6], fk[7]);
            l4.x = packlo(fk[0], fk[1]); l4.y = packlo(fk[2], fk[3]);
            l4.z = packlo(fk[4], fk[5]); l4.w = packlo(fk[6], fk[7]);
            *(uint4*)(sh + KHI + off) = h4;
            *(uint4*)(sh + KLO + off) = l4;
            h4.x = packhi(fv[0], fv[1]); h4.y = packhi(fv[2], fv[3]);
            h4.z = packhi(fv[4], fv[5]); h4.w = packhi(fv[6], fv[7]);
            l4.x = packlo(fv[0], fv[1]); l4.y = packlo(fv[2], fv[3]);
            l4.z = packlo(fv[4], fv[5]); l4.w = packlo(fv[6], fv[7]);
            *(uint4*)(sh + VHI + off) = h4;
            *(uint4*)(sh + VLO + off) = l4;
        }
        __syncthreads();

        // ---- prefetch next K/V tile ----
        if (kt + 1 < ktmax) {
            size_t base = (size_t)((kt + 1) * 64 + frow) * HD + fc;
#pragma unroll
            for (int i = 0; i < 4; ++i) {
                pk[i] = *(const float4*)&kp[base + i * 4];
                pv[i] = *(const float4*)&vp[base + i * 4];
            }
        }

        const int k0g = kt * 64;
        if (k0g <= warp_last_row) {      // skip fully-masked tiles for this warp
            // ---- S = Q K^T (compensated) ----
            float s[8][4];
#pragma unroll
            for (int nt = 0; nt < 8; ++nt)
#pragma unroll
                for (int e = 0; e < 4; ++e) s[nt][e] = 0.0f;

#pragma unroll
            for (int ks = 0; ks < 4; ++ks) {
#pragma unroll
                for (int np = 0; np < 4; ++np) {
                    int r = np * 16 + ((lane >> 4) << 3) + (lane & 7);
                    int g = ks * 2 + ((lane >> 3) & 1);
                    uint32_t off = (uint32_t)r * 128 + (((uint32_t)(g ^ (r & 7))) << 4);
                    uint32_t kh4[4], kl4[4];
                    ldsm4(kh4, shb + KHI + off);
                    ldsm4(kl4, shb + KLO + off);
#pragma unroll
                    for (int t = 0; t < 2; ++t) {
                        int nt = np * 2 + t;
                        mma_bf(s[nt], qh[ks], kh4 + t * 2);
                        mma_bf(s[nt], ql[ks], kh4 + t * 2);
                        mma_bf(s[nt], qh[ks], kl4 + t * 2);
                    }
                }
            }

            const int r0g = q0 + wid * 16 + (lane >> 2);
            const int r1g = r0g + 8;
            if (k0g + 63 > r0g) {        // causal mask on diagonal tiles
#pragma unroll
                for (int nt = 0; nt < 8; ++nt)
#pragma unroll
                    for (int e = 0; e < 2; ++e) {
                        int col = k0g + nt * 8 + ((lane & 3) << 1) + e;
                        if (col > r0g) s[nt][e]     = -1e30f;
                        if (col > r1g) s[nt][2 + e] = -1e30f;
                    }
            }

            // ---- online softmax (rows r0g / r1g; quad = lanes sharing a row) ----
            float mx0 = -1e30f, mx1 = -1e30f;
#pragma unroll
            for (int nt = 0; nt < 8; ++nt) {
                mx0 = fmaxf(mx0, fmaxf(s[nt][0], s[nt][1]));
                mx1 = fmaxf(mx1, fmaxf(s[nt][2], s[nt][3]));
            }
            mx0 = fmaxf(mx0, __shfl_xor_sync(0xffffffffu, mx0, 1));
            mx0 = fmaxf(mx0, __shfl_xor_sync(0xffffffffu, mx0, 2));
            mx1 = fmaxf(mx1, __shfl_xor_sync(0xffffffffu, mx1, 1));
            mx1 = fmaxf(mx1, __shfl_xor_sync(0xffffffffu, mx1, 2));
            float mn0 = fmaxf(m0r, mx0), mn1 = fmaxf(m1r, mx1);
            float a0 = __expf(m0r - mn0), a1 = __expf(m1r - mn1);
            m0r = mn0; m1r = mn1;

            float sum0 = 0.0f, sum1 = 0.0f;
#pragma unroll
            for (int nt = 0; nt < 8; ++nt) {
                s[nt][0] = __expf(s[nt][0] - mn0); sum0 += s[nt][0];
                s[nt][1] = __expf(s[nt][1] - mn0); sum0 += s[nt][1];
                s[nt][2] = __expf(s[nt][2] - mn1); sum1 += s[nt][2];
                s[nt][3] = __expf(s[nt][3] - mn1); sum1 += s[nt][3];
            }
            sum0 += __shfl_xor_sync(0xffffffffu, sum0, 1);
            sum0 += __shfl_xor_sync(0xffffffffu, sum0, 2);
            sum1 += __shfl_xor_sync(0xffffffffu, sum1, 1);
            sum1 += __shfl_xor_sync(0xffffffffu, sum1, 2);
            l0r = l0r * a0 + sum0;
            l1r = l1r * a1 + sum1;
#pragma unroll
            for (int nt = 0; nt < 8; ++nt) {
                o[nt][0] *= a0; o[nt][1] *= a0;
                o[nt][2] *= a1; o[nt][3] *= a1;
            }

            // ---- O += P V (compensated); pack P frags per k-step ----
#pragma unroll
            for (int j = 0; j < 4; ++j) {
                uint32_t ph[4], plo[4];
#pragma unroll
                for (int t = 0; t < 2; ++t) {
                    int nt = j * 2 + t;
                    ph[t * 2 + 0]  = packhi(s[nt][0], s[nt][1]);
                    ph[t * 2 + 1]  = packhi(s[nt][2], s[nt][3]);
                    plo[t * 2 + 0] = packlo(s[nt][0], s[nt][1]);
                    plo[t * 2 + 1] = packlo(s[nt][2], s[nt][3]);
                }
#pragma unroll
                for (int np = 0; np < 4; ++np) {
                    int r = j * 16 + (lane & 15);
                    int g = np * 2 + (lane >> 4);
                    uint32_t off = (uint32_t)r * 128 + (((uint32_t)(g ^ (r & 7))) << 4);
                    uint32_t vh4[4], vl4[4];
                    ldsm4t(vh4, shb + VHI + off);
                    ldsm4t(vl4, shb + VLO + off);
#pragma unroll
                    for (int t = 0; t < 2; ++t) {
                        int nt = np * 2 + t;
                        mma_bf(o[nt], ph,  vh4 + t * 2);
                        mma_bf(o[nt], plo, vh4 + t * 2);
                        mma_bf(o[nt], ph,  vl4 + t * 2);
                    }
                }
            }
        }
    }

    // ---- normalize and write [B,S,D] ----
    const float inv0 = 1.0f / l0r;
    const float inv1 = 1.0f / l1r;
    const int b  = bh >> 4;
    const int h_ = bh & 15;
    const int r0 = q0 + wid * 16 + (lane >> 2);
    size_t base0 = ((size_t)b * SS + r0) * DD + h_ * 64;
    size_t base1 = base0 + (size_t)8 * DD;
#pragma unroll
    for (int nt = 0; nt < 8; ++nt) {
        int col = nt * 8 + ((lane & 3) << 1);
        float2 v0 = { o[nt][0] * inv0, o[nt][1] * inv0 };
        float2 v1 = { o[nt][2] * inv1, o[nt][3] * inv1 };
        *(float2*)&g_attn[base0 + col] = v0;
        *(float2*)&g_attn[base1 + col] = v1;
    }
}

// ---------------------------------------------------------------------------
extern "C" void kernel_launch(void* const* d_in, const int* in_sizes, int n_in,
                              void* d_out, int out_size)
{
    const float* h  = (const float*)d_in[0];
    const float* Wq = (const float*)d_in[1];
    const float* bq = (const float*)d_in[2];
    const float* Wk = (const float*)d_in[3];
    const float* bk = (const float*)d_in[4];
    const float* Wv = (const float*)d_in[5];
    const float* bv = (const float*)d_in[6];
    const float* Wo = (const float*)d_in[7];
    const float* bo = (const float*)d_in[8];
    float* out = (float*)d_out;

    float *dq, *dk, *dv, *da;
    cudaGetSymbolAddress((void**)&dq, g_q);
    cudaGetSymbolAddress((void**)&dk, g_k);
    cudaGetSymbolAddress((void**)&dv, g_v);
    cudaGetSymbolAddress((void**)&da, g_attn);

    dim3 ggrid(DD / 128, (BB * SS) / 128);   // (8, 32)

    gemm_mma<<<ggrid, 256>>>(h, Wq, bq, dq, 0);
    gemm_mma<<<ggrid, 256>>>(h, Wk, bk, dk, 0);
    gemm_mma<<<ggrid, 256>>>(h, Wv, bv, dv, 0);

    attn_mma<<<dim3(SS / 128, BB * HH), 256>>>();

    gemm_mma<<<ggrid, 256>>>(da, Wo, bo, out, 1);
}